// round 6
// baseline (speedup 1.0000x reference)
#include <cuda_runtime.h>
#include <cstdint>

// COO SpMM via direct fixed-capacity row buckets, D = 64.
// R6: two kernels only. g_count/g_ovf_count are zero-initialized at module
//     load and self-restored by spmm (each warp re-zeroes its row's count
//     after reading it), so no zeroing kernel and no overflow kernel.

#define D_DIM    64
#define N_MAX    100000
#define E_MAX    3200000
#define CAP      128          // slots per row (avg degree 32, P(deg>128)~1e-40)
#define OVF_CAP  8192

__device__ int  g_count[N_MAX];                  // zero-init at load
__device__ int2 g_bucket[(size_t)N_MAX * CAP];   // {col, float bits of val}
__device__ int  g_ovf_count;                     // zero-init at load
__device__ int4 g_ovf[OVF_CAP];                  // {row, col, valbits, 0}

// ---- Phase 1: bucket scatter -------------------------------------------------

__global__ void scatter_bucket(const int* __restrict__ idx,
                               const float* __restrict__ vals, int E) {
    int e = blockIdx.x * blockDim.x + threadIdx.x;
    if (e >= E) return;
    int row = idx[e];
    int col = idx[E + e];
    int vb  = __float_as_int(vals[e]);
    int pos = atomicAdd(&g_count[row], 1);
    if (pos < CAP) {
        g_bucket[(size_t)row * CAP + pos] = make_int2(col, vb);
    } else {
        int o = atomicAdd(&g_ovf_count, 1);
        if (o < OVF_CAP) g_ovf[o] = make_int4(row, col, vb, 0);
    }
}

// ---- Phase 2: one warp per row; restores counts to zero for next replay ------

__global__ void __launch_bounds__(256) spmm_bucket(const float* __restrict__ b,
                                                   float* __restrict__ out, int n) {
    int warp = (blockIdx.x * blockDim.x + threadIdx.x) >> 5;
    int lane = threadIdx.x & 31;
    if (warp >= n) return;

    int cnt = g_count[warp];
    if (lane == 0) g_count[warp] = 0;   // self-restore for next graph replay
    int novf = g_ovf_count;             // hot L2 line, expected 0
    if (cnt > CAP) cnt = CAP;

    const int2*   __restrict__ bkt = g_bucket + (size_t)warp * CAP;
    const float2* __restrict__ B   = reinterpret_cast<const float2*>(b);
    float a0 = 0.f, a1 = 0.f;

    #pragma unroll 4
    for (int i = 0; i < cnt; i++) {
        int2  p  = bkt[i];                    // broadcast load (L1-hot)
        float v  = __int_as_float(p.y);
        float2 bv = __ldg(&B[(long long)p.x * 32 + lane]);
        a0 = fmaf(v, bv.x, a0);
        a1 = fmaf(v, bv.y, a1);
    }

    // Overflow edges (unreachable for this input; CAP >> max degree). Handled
    // here — before this row's store — which is the only ordering-safe point.
    if (novf != 0) {
        if (novf > OVF_CAP) novf = OVF_CAP;
        for (int k = 0; k < novf; k++) {
            int4 ov = g_ovf[k];
            if (ov.x == warp) {
                float v = __int_as_float(ov.z);
                float2 bv = __ldg(&B[(long long)ov.y * 32 + lane]);
                a0 = fmaf(v, bv.x, a0);
                a1 = fmaf(v, bv.y, a1);
            }
        }
    }
    if (warp == 0 && lane == 0) g_ovf_count = 0;   // restore (always already 0)

    reinterpret_cast<float2*>(out)[(long long)warp * 32 + lane] =
        make_float2(a0, a1);
}

// ---- Launch ------------------------------------------------------------------

extern "C" void kernel_launch(void* const* d_in, const int* in_sizes, int n_in,
                              void* d_out, int out_size) {
    const int*   idx  = (const int*)d_in[0];          // [2, E]
    const float* vals = (const float*)d_in[1];        // [E]
    const float* b    = (const float*)d_in[n_in - 1]; // [N, 64]
    float*       out  = (float*)d_out;

    int E = in_sizes[1];
    int N = out_size / D_DIM;
    if (E > E_MAX) E = E_MAX;
    if (N > N_MAX) N = N_MAX;

    int eg = (E + 255) / 256;

    scatter_bucket<<<eg, 256>>>(idx, vals, E);

    long long threads = (long long)N * 32;
    spmm_bucket<<<(unsigned)((threads + 255) / 256), 256>>>(b, out, N);
}

// round 7
// speedup vs baseline: 4.1987x; 4.1987x over previous
#include <cuda_runtime.h>
#include <cstdint>

// COO SpMM via direct fixed-capacity row buckets, D = 64.
// R7: hot kernels are exactly R5's (known-good 110.7us). zero_counts is
//     deleted: the tail kernel (overflow apply, normally empty) also re-zeroes
//     g_count for the next graph replay. First launch relies on zero-init of
//     __device__ globals.

#define D_DIM    64
#define N_MAX    100000
#define E_MAX    3200000
#define CAP      128          // slots per row (avg degree 32, P(deg>128)~0)
#define OVF_CAP  8192

__device__ int  g_count[N_MAX];                  // zero-init at load
__device__ int2 g_bucket[(size_t)N_MAX * CAP];   // {col, float bits of val}
__device__ int  g_ovf_count;                     // zero-init at load
__device__ int4 g_ovf[OVF_CAP];                  // {row, col, valbits, 0}

// ---- Phase 1: bucket scatter -------------------------------------------------

__global__ void scatter_bucket(const int* __restrict__ idx,
                               const float* __restrict__ vals, int E) {
    int e = blockIdx.x * blockDim.x + threadIdx.x;
    if (e >= E) return;
    int row = idx[e];
    int col = idx[E + e];
    int vb  = __float_as_int(vals[e]);
    int pos = atomicAdd(&g_count[row], 1);
    if (pos < CAP) {
        g_bucket[(size_t)row * CAP + pos] = make_int2(col, vb);
    } else {
        int o = atomicAdd(&g_ovf_count, 1);
        if (o < OVF_CAP) g_ovf[o] = make_int4(row, col, vb, 0);
    }
}

// ---- Phase 2: one warp per row, broadcast edge loads, plain stores -----------
// EXACT R5 body — do not perturb: the unroll-4 gather MLP is what keeps this
// kernel at the L2 bandwidth cap.

__global__ void __launch_bounds__(256) spmm_bucket(const float* __restrict__ b,
                                                   float* __restrict__ out, int n) {
    int warp = (blockIdx.x * blockDim.x + threadIdx.x) >> 5;
    int lane = threadIdx.x & 31;
    if (warp >= n) return;

    int cnt = g_count[warp];
    if (cnt > CAP) cnt = CAP;

    const int2*   __restrict__ bkt = g_bucket + (size_t)warp * CAP;
    const float2* __restrict__ B   = reinterpret_cast<const float2*>(b);
    float a0 = 0.f, a1 = 0.f;

    #pragma unroll 4
    for (int i = 0; i < cnt; i++) {
        int2  p  = bkt[i];                    // broadcast load (L1-hot)
        float v  = __int_as_float(p.y);
        float2 bv = __ldg(&B[(long long)p.x * 32 + lane]);
        a0 = fmaf(v, bv.x, a0);
        a1 = fmaf(v, bv.y, a1);
    }

    reinterpret_cast<float2*>(out)[(long long)warp * 32 + lane] =
        make_float2(a0, a1);
}

// ---- Phase 3 (tail): apply overflow (normally none) + restore counters -------

__global__ void tail_cleanup(const float* __restrict__ b,
                             float* __restrict__ out, int n) {
    int t = blockIdx.x * blockDim.x + threadIdx.x;
    int stride = gridDim.x * blockDim.x;

    // Overflow edges: 16 threads per edge, float4 per thread (expected 0 work).
    int novf = g_ovf_count;
    if (novf > OVF_CAP) novf = OVF_CAP;
    for (int s = t; s < novf * 16; s += stride) {
        int  k = s >> 4;
        int  j = (s & 15) << 2;
        int4 ov = g_ovf[k];
        float v = __int_as_float(ov.z);
        const float4 bv =
            *reinterpret_cast<const float4*>(b + (long long)ov.y * D_DIM + j);
        float* dst = out + (long long)ov.x * D_DIM + j;
        asm volatile("red.global.add.v4.f32 [%0], {%1, %2, %3, %4};"
                     :: "l"(dst), "f"(bv.x * v), "f"(bv.y * v),
                        "f"(bv.z * v), "f"(bv.w * v)
                     : "memory");
    }

    // Restore state for the next graph replay (vectorized zero of g_count).
    int4* cz = reinterpret_cast<int4*>(g_count);
    for (int i = t; i < n / 4; i += stride)
        cz[i] = make_int4(0, 0, 0, 0);
    for (int i = (n / 4) * 4 + t; i < n; i += stride)
        g_count[i] = 0;
    if (t == 0) g_ovf_count = 0;
}

// ---- Launch ------------------------------------------------------------------

extern "C" void kernel_launch(void* const* d_in, const int* in_sizes, int n_in,
                              void* d_out, int out_size) {
    const int*   idx  = (const int*)d_in[0];          // [2, E]
    const float* vals = (const float*)d_in[1];        // [E]
    const float* b    = (const float*)d_in[n_in - 1]; // [N, 64]
    float*       out  = (float*)d_out;

    int E = in_sizes[1];
    int N = out_size / D_DIM;
    if (E > E_MAX) E = E_MAX;
    if (N > N_MAX) N = N_MAX;

    int eg = (E + 255) / 256;

    scatter_bucket<<<eg, 256>>>(idx, vals, E);

    long long threads = (long long)N * 32;
    spmm_bucket<<<(unsigned)((threads + 255) / 256), 256>>>(b, out, N);
    tail_cleanup<<<148, 256>>>(b, out, N);
}